// round 16
// baseline (speedup 1.0000x reference)
#include <cuda_runtime.h>
#include <math.h>

#define NFFT  2048
#define TPB   256
#define EPT   (NFFT / TPB)        // 8 elements per thread
#define MAXB  64
#define NS    81                  // number of scales (J=80 -> 81)
#define WSZ   94                  // sliding window = 32*3 - 2
#define NOUT  (NFFT - WSZ + 1)    // 1955

#define PI_F  3.14159265358979323846f
#define TWO_PI_F 6.28318530717958647692f

// SMEM padding: 1 extra element per 8 -> conflict-free radix-8 exchanges
#define PIDX(i) ((i) + ((i) >> 3))
#define PADN  2304                // PIDX(2047)+1 = 2303, rounded
#define SMEM_DYN (4 * PADN * (int)sizeof(unsigned long long))   // 73728 B

typedef unsigned long long u64;

// ---------------- scratch (static device globals; no runtime alloc) ----------
__device__ float2 g_tw[256];                      // twiddles e^{-i pi j / 1024}
__device__ float2 g_yh[MAXB * 2 * NFFT];          // forward FFT of normalized inputs
// interleaved smooth outputs: [b][scale][t][0] = (T1,T2), [b][scale][t][1] = T12
__device__ float2 g_Tp[(size_t)MAXB * NS * NFFT * 2];
__device__ float  g_coh[MAXB * NFFT];             // coherence summed over scales

// ---------------- scalar complex helpers (K1) -----------------------------------
__device__ __forceinline__ float2 cadd(float2 a, float2 b){ return make_float2(a.x+b.x, a.y+b.y); }
__device__ __forceinline__ float2 csub(float2 a, float2 b){ return make_float2(a.x-b.x, a.y-b.y); }
__device__ __forceinline__ float2 cmul(float2 a, float2 b){
  return make_float2(a.x*b.x - a.y*b.y, a.x*b.y + a.y*b.x);
}
__device__ __forceinline__ float2 rotm(float2 a, bool inv){
  return inv ? make_float2(-a.y, a.x) : make_float2(a.y, -a.x);
}

__device__ __forceinline__ void bfly8_tail(float2 t0, float2 t1, float2 t2, float2 t3,
                                           float2 t4, float2 t5, float2 t6, float2 t7,
                                           float2* b, bool inv) {
  float2 u0 = cadd(t0,t2), u2 = csub(t0,t2);
  float2 u1 = cadd(t1,t3), u3 = rotm(csub(t1,t3), inv);
  b[0] = cadd(u0,u1); b[4] = csub(u0,u1);
  b[2] = cadd(u2,u3); b[6] = csub(u2,u3);
  float2 v0 = cadd(t4,t6), v2 = csub(t4,t6);
  float2 v1 = cadd(t5,t7), v3 = rotm(csub(t5,t7), inv);
  b[1] = cadd(v0,v1); b[5] = csub(v0,v1);
  b[3] = cadd(v2,v3); b[7] = csub(v2,v3);
}

__device__ __forceinline__ void bfly8(const float2* a, float2* b, bool inv) {
  const float C = 0.70710678118654752440f;
  float2 t0 = cadd(a[0],a[4]), t4 = csub(a[0],a[4]);
  float2 t1 = cadd(a[1],a[5]), t5 = csub(a[1],a[5]);
  float2 t2 = cadd(a[2],a[6]), t6 = csub(a[2],a[6]);
  float2 t3 = cadd(a[3],a[7]), t7 = csub(a[3],a[7]);
  const float2 w81 = inv ? make_float2(C,  C) : make_float2(C, -C);
  const float2 w83 = inv ? make_float2(-C, C) : make_float2(-C,-C);
  bfly8_tail(t0, t1, t2, t3, t4, cmul(t5, w81), rotm(t6, inv), cmul(t7, w83), b, inv);
}

struct W7 { float2 w1,w2,w3,w4,w5,w6,w7; };
__device__ __forceinline__ W7 make_w7(float2 w1) {
  W7 w;
  w.w1 = w1;
  w.w2 = cmul(w1, w1);
  w.w3 = cmul(w.w2, w1);
  w.w4 = cmul(w.w2, w.w2);
  w.w5 = cmul(w.w3, w.w2);
  w.w6 = cmul(w.w3, w.w3);
  w.w7 = cmul(w.w4, w.w3);
  return w;
}
__device__ __forceinline__ void apply_w7(float2* b, const W7& w) {
  b[1] = cmul(b[1], w.w1); b[2] = cmul(b[2], w.w2); b[3] = cmul(b[3], w.w3);
  b[4] = cmul(b[4], w.w4); b[5] = cmul(b[5], w.w5); b[6] = cmul(b[6], w.w6);
  b[7] = cmul(b[7], w.w7);
}

// ================= scalar single-stream FFT (K1 only) ===========================
__device__ __forceinline__ void stage1_reg(const float2* x, float2* dst,
                                           const float2* __restrict__ tw, int tid, bool inv) {
  float2 b[8];
  bfly8(x, b, inv);
  float2 w1 = tw[tid];
  if (inv) w1.y = -w1.y;
  W7 w = make_w7(w1);
  apply_w7(b, w);
  const int wb = 8 * tid;
  #pragma unroll
  for (int j = 0; j < 8; ++j) dst[PIDX(wb + j)] = b[j];
}

template<int S>
__device__ __forceinline__ void stage8(const float2* __restrict__ src, float2* __restrict__ dst,
                                       const float2* __restrict__ tw, int tid, bool inv) {
  const int p = tid / S;
  const int q = tid - p * S;
  const int rb = q + S * p;
  float2 a[8];
  #pragma unroll
  for (int k = 0; k < 8; ++k) a[k] = src[PIDX(rb + 256 * k)];
  float2 b[8];
  bfly8(a, b, inv);
  float2 w1 = tw[p * S];
  if (inv) w1.y = -w1.y;
  W7 w = make_w7(w1);
  apply_w7(b, w);
  const int wb = q + S * 8 * p;
  #pragma unroll
  for (int j = 0; j < 8; ++j) dst[PIDX(wb + j * S)] = b[j];
}

__device__ __forceinline__ void stage4_reg(const float2* __restrict__ src, float2* y,
                                           int tid, bool inv) {
  #pragma unroll
  for (int rr = 0; rr < 2; ++rr) {
    const int q = tid + rr * TPB;
    float2 a0 = src[PIDX(q)];
    float2 a1 = src[PIDX(q +  512)];
    float2 a2 = src[PIDX(q + 1024)];
    float2 a3 = src[PIDX(q + 1536)];
    float2 t0 = cadd(a0,a2), t1 = csub(a0,a2);
    float2 t2 = cadd(a1,a3), t3 = rotm(csub(a1,a3), inv);
    y[rr + 0] = cadd(t0,t2);
    y[rr + 2] = cadd(t1,t3);
    y[rr + 4] = csub(t0,t2);
    y[rr + 6] = csub(t1,t3);
  }
}

__device__ __forceinline__ void fft_reg(float2* x, float2* sA, float2* sB,
                                        const float2* __restrict__ tw, int tid, bool inv) {
  __syncthreads();
  stage1_reg(x, sB, tw, tid, inv);  __syncthreads();
  stage8<8> (sB, sA, tw, tid, inv); __syncthreads();
  stage8<64>(sA, sB, tw, tid, inv); __syncthreads();
  stage4_reg(sB, x, tid, inv);
}

// ================= f32x2 packed dual-stream machinery (K2) ======================
// Lane lo = stream 1, lane hi = stream 2. Complex value = {re-plane, im-plane}.
__device__ __forceinline__ u64 pk2(float lo, float hi){
  u64 r; asm("mov.b64 %0,{%1,%2};" : "=l"(r) : "f"(lo), "f"(hi)); return r;
}
__device__ __forceinline__ void upk2(u64 v, float& lo, float& hi){
  asm("mov.b64 {%0,%1},%2;" : "=f"(lo), "=f"(hi) : "l"(v));
}
__device__ __forceinline__ u64 add2(u64 a, u64 b){
  u64 r; asm("add.rn.f32x2 %0,%1,%2;" : "=l"(r) : "l"(a), "l"(b)); return r;
}
__device__ __forceinline__ u64 mul2(u64 a, u64 b){
  u64 r; asm("mul.rn.f32x2 %0,%1,%2;" : "=l"(r) : "l"(a), "l"(b)); return r;
}
__device__ __forceinline__ u64 fma2(u64 a, u64 b, u64 c){
  u64 r; asm("fma.rn.f32x2 %0,%1,%2,%3;" : "=l"(r) : "l"(a), "l"(b), "l"(c)); return r;
}
#define KNEG1_2 0xBF800000BF800000ULL      // (-1.f, -1.f)
#define KC_2    0x3F3504F33F3504F3ULL      // ( sqrt(.5),  sqrt(.5))
#define KNC_2   0xBF3504F3BF3504F3ULL      // (-sqrt(.5), -sqrt(.5))
__device__ __forceinline__ u64 sub2(u64 a, u64 b){ return fma2(b, (u64)KNEG1_2, a); }
__device__ __forceinline__ u64 neg2(u64 a){ return mul2(a, (u64)KNEG1_2); }

struct c2 { u64 re, im; };
__device__ __forceinline__ c2 cadd2(c2 a, c2 b){ return { add2(a.re,b.re), add2(a.im,b.im) }; }
__device__ __forceinline__ c2 csub2(c2 a, c2 b){ return { sub2(a.re,b.re), sub2(a.im,b.im) }; }
__device__ __forceinline__ c2 rotm2(c2 a, bool inv){
  return inv ? c2{ neg2(a.im), a.re } : c2{ a.im, neg2(a.re) };
}
// multiply by w81 = (C,-C) fwd / (C,C) inv
__device__ __forceinline__ c2 cmul_w81p(c2 a, bool inv){
  if (!inv) return { mul2(add2(a.re,a.im), (u64)KC_2), mul2(sub2(a.im,a.re), (u64)KC_2) };
  else      return { mul2(sub2(a.re,a.im), (u64)KC_2), mul2(add2(a.re,a.im), (u64)KC_2) };
}
// multiply by w83 = (-C,-C) fwd / (-C,C) inv
__device__ __forceinline__ c2 cmul_w83p(c2 a, bool inv){
  if (!inv) return { mul2(sub2(a.im,a.re), (u64)KC_2), mul2(add2(a.re,a.im), (u64)KNC_2) };
  else      return { mul2(add2(a.re,a.im), (u64)KNC_2), mul2(sub2(a.re,a.im), (u64)KC_2) };
}
// multiply by scalar twiddle w (same for both lanes)
__device__ __forceinline__ c2 cmul2s(c2 a, float2 w){
  u64 wr  = pk2(w.x,  w.x);
  u64 wi  = pk2(w.y,  w.y);
  u64 nwi = pk2(-w.y, -w.y);
  return { fma2(a.im, nwi, mul2(a.re, wr)),
           fma2(a.im, wr,  mul2(a.re, wi)) };
}

__device__ __forceinline__ void bfly8p_tail(c2 t0, c2 t1, c2 t2, c2 t3,
                                            c2 t4, c2 t5, c2 t6, c2 t7,
                                            c2* b, bool inv){
  c2 u0 = cadd2(t0,t2), u2 = csub2(t0,t2);
  c2 u1 = cadd2(t1,t3), u3 = rotm2(csub2(t1,t3), inv);
  b[0] = cadd2(u0,u1); b[4] = csub2(u0,u1);
  b[2] = cadd2(u2,u3); b[6] = csub2(u2,u3);
  c2 v0 = cadd2(t4,t6), v2 = csub2(t4,t6);
  c2 v1 = cadd2(t5,t7), v3 = rotm2(csub2(t5,t7), inv);
  b[1] = cadd2(v0,v1); b[5] = csub2(v0,v1);
  b[3] = cadd2(v2,v3); b[7] = csub2(v2,v3);
}

__device__ __forceinline__ void bfly8p(const c2* a, c2* b, bool inv){
  c2 t0 = cadd2(a[0],a[4]), t4 = csub2(a[0],a[4]);
  c2 t1 = cadd2(a[1],a[5]), t5 = csub2(a[1],a[5]);
  c2 t2 = cadd2(a[2],a[6]), t6 = csub2(a[2],a[6]);
  c2 t3 = cadd2(a[3],a[7]), t7 = csub2(a[3],a[7]);
  bfly8p_tail(t0,t1,t2,t3,t4, cmul_w81p(t5,inv), rotm2(t6,inv), cmul_w83p(t7,inv), b, inv);
}

// half-spectrum: a[4..7] == 0
__device__ __forceinline__ void bfly8p_half(const c2* a, c2* b, bool inv){
  bfly8p_tail(a[0],a[1],a[2],a[3], a[0],
              cmul_w81p(a[1],inv), rotm2(a[2],inv), cmul_w83p(a[3],inv), b, inv);
}

// scalar twiddle power tree, packed application
__device__ __forceinline__ void applytw(c2* b, float2 w1){
  float2 w2 = cmul(w1,w1), w3 = cmul(w2,w1), w4 = cmul(w2,w2);
  float2 w5 = cmul(w3,w2), w6 = cmul(w3,w3), w7 = cmul(w4,w3);
  b[1] = cmul2s(b[1], w1); b[2] = cmul2s(b[2], w2); b[3] = cmul2s(b[3], w3);
  b[4] = cmul2s(b[4], w4); b[5] = cmul2s(b[5], w5); b[6] = cmul2s(b[6], w6);
  b[7] = cmul2s(b[7], w7);
}

template<bool HALF>
__device__ __forceinline__ void st1p(const c2* x, u64* dRe, u64* dIm,
                                     const float2* __restrict__ tw, int tid, bool inv){
  c2 b[8];
  if (HALF) bfly8p_half(x, b, inv); else bfly8p(x, b, inv);
  float2 w1 = tw[tid]; if (inv) w1.y = -w1.y;
  applytw(b, w1);
  const int wb = 8 * tid;
  #pragma unroll
  for (int j = 0; j < 8; ++j) { dRe[PIDX(wb+j)] = b[j].re; dIm[PIDX(wb+j)] = b[j].im; }
}

template<int S>
__device__ __forceinline__ void st8p(const u64* __restrict__ sRe, const u64* __restrict__ sIm,
                                     u64* __restrict__ dRe, u64* __restrict__ dIm,
                                     const float2* __restrict__ tw, int tid, bool inv){
  const int p = tid / S;
  const int q = tid - p * S;
  const int rb = q + S * p;
  c2 a[8];
  #pragma unroll
  for (int k = 0; k < 8; ++k) {
    a[k].re = sRe[PIDX(rb + 256*k)];
    a[k].im = sIm[PIDX(rb + 256*k)];
  }
  c2 b[8];
  bfly8p(a, b, inv);
  float2 w1 = tw[p * S]; if (inv) w1.y = -w1.y;
  applytw(b, w1);
  const int wb = q + S * 8 * p;
  #pragma unroll
  for (int j = 0; j < 8; ++j) { dRe[PIDX(wb+j*S)] = b[j].re; dIm[PIDX(wb+j*S)] = b[j].im; }
}

__device__ __forceinline__ void st4p(const u64* __restrict__ sRe, const u64* __restrict__ sIm,
                                     c2* y, int tid, bool inv){
  #pragma unroll
  for (int rr = 0; rr < 2; ++rr) {
    const int q = tid + rr * TPB;
    c2 a0 = { sRe[PIDX(q)],        sIm[PIDX(q)]        };
    c2 a1 = { sRe[PIDX(q +  512)], sIm[PIDX(q +  512)] };
    c2 a2 = { sRe[PIDX(q + 1024)], sIm[PIDX(q + 1024)] };
    c2 a3 = { sRe[PIDX(q + 1536)], sIm[PIDX(q + 1536)] };
    c2 t0 = cadd2(a0,a2), t1 = csub2(a0,a2);
    c2 t2 = cadd2(a1,a3), t3 = rotm2(csub2(a1,a3), inv);
    y[rr + 0] = cadd2(t0,t2);
    y[rr + 2] = cadd2(t1,t3);
    y[rr + 4] = csub2(t0,t2);
    y[rr + 6] = csub2(t1,t3);
  }
}

// packed dual FFT: x[r] = element (tid + 256 r) of BOTH streams. 4 syncs.
template<bool HALF>
__device__ __forceinline__ void fftp(c2* x, u64* pRe, u64* pIm, u64* qRe, u64* qIm,
                                     const float2* __restrict__ tw, int tid, bool inv){
  __syncthreads();                                  // ping free of previous readers
  st1p<HALF>(x, pRe, pIm, tw, tid, inv);  __syncthreads();
  st8p<8>  (pRe, pIm, qRe, qIm, tw, tid, inv); __syncthreads();
  st8p<64> (qRe, qIm, pRe, pIm, tw, tid, inv); __syncthreads();
  st4p(pRe, pIm, x, tid, inv);
}

// ---------------- K0: build 256-entry twiddle table (double precision) ---------
__global__ void kern_init_tw() {
  const int j = threadIdx.x;
  double a = -3.14159265358979323846 * (double)j / 1024.0;
  g_tw[j] = make_float2((float)cos(a), (float)sin(a));
}

// ---------------- K1: normalize + forward FFT of each input signal ------------
__global__ void kern_fft_input(const float* __restrict__ x) {
  __shared__ float2 sA[PADN];
  __shared__ float2 sB[PADN];
  __shared__ float2 tw[256];
  __shared__ float  red[TPB];
  const int bc  = blockIdx.x;   // b*2 + channel
  const int tid = threadIdx.x;

  tw[tid] = g_tw[tid];

  const float* y = x + (size_t)bc * NFFT;
  float vals[EPT];
  float sum = 0.f, sumsq = 0.f;
  #pragma unroll
  for (int r = 0; r < EPT; ++r) {
    float v = y[tid + r * TPB];
    vals[r] = v;
    sum += v;
    sumsq += v * v;
  }
  red[tid] = sum; __syncthreads();
  for (int o = TPB / 2; o > 0; o >>= 1) { if (tid < o) red[tid] += red[tid + o]; __syncthreads(); }
  float mean = red[0] * (1.0f / NFFT);
  __syncthreads();
  red[tid] = sumsq; __syncthreads();
  for (int o = TPB / 2; o > 0; o >>= 1) { if (tid < o) red[tid] += red[tid + o]; __syncthreads(); }
  float var = red[0] * (1.0f / NFFT) - mean * mean;
  float istd = rsqrtf(var);

  float2 z[EPT];
  #pragma unroll
  for (int r = 0; r < EPT; ++r)
    z[r] = make_float2((vals[r] - mean) * istd, 0.f);

  fft_reg(z, sA, sB, tw, tid, false);

  #pragma unroll
  for (int r = 0; r < EPT; ++r)
    g_yh[(size_t)bc * NFFT + tid + r * TPB] = z[r];
}

// ---------------- K2: per (batch, scale) CWT + time smoothing (f32x2 packed) ---
__global__ void __launch_bounds__(TPB) kern_scale() {
  extern __shared__ u64 dyn8[];
  u64* pRe = dyn8;
  u64* pIm = dyn8 + PADN;
  u64* qRe = dyn8 + 2 * PADN;
  u64* qIm = dyn8 + 3 * PADN;
  __shared__ float2 tw[256];
  const int si  = blockIdx.x;   // scale index
  const int b   = blockIdx.y;   // batch
  const int tid = threadIdx.x;

  tw[tid] = g_tw[tid];

  const double s0d = 2.0 * 0.1 * (6.0 + sqrt(38.0)) / (4.0 * 3.14159265358979323846);
  const float  sc    = (float)(s0d * exp2(0.125 * (double)si));
  const float  inv_s = 1.0f / sc;
  const float  norm  = sqrtf(TWO_PI_F * sc * 10.0f) * 0.75112554446494248f;
  const float  sdt   = sc * 10.0f;
  const float  INVN  = 1.0f / (float)NFFT;
  const float  pscale = INVN * INVN * inv_s;   // 1/N per ifft (x2) and 1/s

  c2 x[EPT];

  // --- spectra: lane lo = channel 0 (W1), lane hi = channel 1 (W2); k in [1,1024)
  #pragma unroll
  for (int r = 0; r < 4; ++r) {
    int k = tid + r * TPB;
    float v1x = 0.f, v1y = 0.f, v2x = 0.f, v2y = 0.f;
    if (k >= 1) {
      float w = TWO_PI_F * (float)k * (1.0f / 204.8f);
      float d = sc * w - 6.0f;
      float g = norm * __expf(-0.5f * d * d);
      float2 y1 = g_yh[(size_t)(b * 2) * NFFT + k];
      float2 y2 = g_yh[(size_t)(b * 2 + 1) * NFFT + k];
      v1x = y1.x * g; v1y = y1.y * g;
      v2x = y2.x * g; v2y = y2.y * g;
    }
    x[r].re = pk2(v1x, v2x);
    x[r].im = pk2(v1y, v2y);
  }
  // x[4..7] are zero in HALF mode (not read by bfly8p_half at stage 1)

  fftp<true>(x, pRe, pIm, qRe, qIm, tw, tid, true);   // -> W1 (lo), W2 (hi), unscaled

  // --- products: new lane lo = P = |W1|^2 + i|W2|^2 ; lane hi = C = W1*conj(W2)
  #pragma unroll
  for (int r = 0; r < EPT; ++r) {
    float w1x, w2x, w1y, w2y;
    upk2(x[r].re, w1x, w2x);
    upk2(x[r].im, w1y, w2y);
    float p1 = (w1x * w1x + w1y * w1y) * pscale;
    float p2 = (w2x * w2x + w2y * w2y) * pscale;
    float cr = (w1x * w2x + w1y * w2y) * pscale;
    float ci = (w1y * w2x - w1x * w2y) * pscale;
    x[r].re = pk2(p1, cr);
    x[r].im = pk2(p2, ci);
  }

  const size_t base = ((size_t)b * NS + si) * NFFT;

  fftp<false>(x, pRe, pIm, qRe, qIm, tw, tid, false);

  // --- Gaussian time filter (incl. 1/N of the subsequent inverse FFT)
  #pragma unroll
  for (int r = 0; r < EPT; ++r) {
    int k = tid + r * TPB;
    float fk = (float)(k < NFFT / 2 ? k : k - NFFT) * (1.0f / NFFT);
    float kk = TWO_PI_F * fk;
    float F = __expf(-0.5f * sdt * sdt * kk * kk) * INVN;
    u64 F2 = pk2(F, F);
    x[r].re = mul2(x[r].re, F2);
    x[r].im = mul2(x[r].im, F2);
  }

  fftp<false>(x, pRe, pIm, qRe, qIm, tw, tid, true);

  // --- stores: lane lo -> (T1,T2), lane hi -> T12
  #pragma unroll
  for (int r = 0; r < EPT; ++r) {
    const int idx = tid + r * TPB;
    float t1v, t12r, t2v, t12i;
    upk2(x[r].re, t1v, t12r);
    upk2(x[r].im, t2v, t12i);
    g_Tp[(base + idx) * 2]     = make_float2(t1v, t2v);
    g_Tp[(base + idx) * 2 + 1] = make_float2(t12r, t12i);
  }
}

// ---------------- K3: scale smoothing + coherence + sum over scales -----------
__global__ void __launch_bounds__(TPB) kern_coh() {
  const int b   = blockIdx.y;
  const int sub = threadIdx.x & 1;                    // 0: (T1,T2), 1: T12
  const int t   = blockIdx.x * (TPB / 2) + (threadIdx.x >> 1);
  const size_t base = ((size_t)b * NS * NFFT + t) * 2 + sub;
  const size_t step = (size_t)NFFT * 2;

  float ru[10], rv[10];
  float su = 0.f, sv = 0.f;

  #pragma unroll
  for (int j = 0; j < 4; ++j) {
    float2 d = g_Tp[base + (size_t)j * step];
    ru[j] = d.x; rv[j] = d.y; su += d.x; sv += d.y;
  }

  float acc = 0.f;
  #pragma unroll
  for (int i = 0; i < NS; ++i) {
    const int jo = i - 6;
    if (jo >= 0) {
      const int ro = jo % 10;
      su -= ru[ro]; sv -= rv[ro];
    }
    const int jn = i + 4;
    if (jn < NS) {
      float2 d = g_Tp[base + (size_t)jn * step];
      const int rn = jn % 10;
      ru[rn] = d.x; rv[rn] = d.y; su += d.x; sv += d.y;
    }
    float eu = su, ev = sv;
    const int jl = i - 5;
    if (jl >= 0) {
      const int rl = jl % 10;
      eu -= 0.5f * ru[rl]; ev -= 0.5f * rv[rl];
    }
    if (jn < NS) {
      const int rn = jn % 10;
      eu -= 0.5f * ru[rn]; ev -= 0.5f * rv[rn];
    }
    float val = sub ? (eu * eu + ev * ev) : __fdividef(1.0f, eu * ev);
    float other = __shfl_xor_sync(0xffffffffu, val, 1);
    acc += val * other;
  }
  if (!sub) g_coh[(size_t)b * NFFT + t] = acc;
}

// ---------------- K4: sliding window sum (WSZ=94), incremental -----------------
__global__ void __launch_bounds__(TPB) kern_slide(float* __restrict__ out) {
  __shared__ float sc[NFFT];
  __shared__ float so[NOUT];
  const int b = blockIdx.x;
  const int tid = threadIdx.x;
  #pragma unroll
  for (int r = 0; r < EPT; ++r)
    sc[tid + r * TPB] = g_coh[(size_t)b * NFFT + tid + r * TPB];
  __syncthreads();

  const int i0 = tid * 8;
  if (i0 < NOUT) {
    float s = 0.f;
    #pragma unroll
    for (int k = 0; k < WSZ; ++k) s += sc[i0 + k];
    so[i0] = s;
    const int lim = (NOUT - i0 < 8) ? (NOUT - i0) : 8;
    for (int r = 1; r < lim; ++r) {
      s += sc[i0 + r - 1 + WSZ] - sc[i0 + r - 1];
      so[i0 + r] = s;
    }
  }
  __syncthreads();
  for (int i = tid; i < NOUT; i += TPB)
    out[(size_t)b * NOUT + i] = so[i];
}

// ---------------- launch -------------------------------------------------------
extern "C" void kernel_launch(void* const* d_in, const int* in_sizes, int n_in,
                              void* d_out, int out_size) {
  const float* x = (const float*)d_in[0];
  int B = in_sizes[0] / (2 * NFFT);
  if (B > MAXB) B = MAXB;
  if (B <= 0) return;

  cudaFuncSetAttribute(kern_scale, cudaFuncAttributeMaxDynamicSharedMemorySize, SMEM_DYN);

  kern_init_tw<<<1, 256>>>();
  kern_fft_input<<<B * 2, TPB>>>(x);
  kern_scale<<<dim3(NS, B), TPB, SMEM_DYN>>>();
  kern_coh<<<dim3(NFFT / (TPB / 2), B), TPB>>>();
  kern_slide<<<B, TPB>>>((float*)d_out);
}

// round 17
// speedup vs baseline: 1.1662x; 1.1662x over previous
#include <cuda_runtime.h>
#include <cuda_bf16.h>
#include <math.h>

#define NFFT  2048
#define TPB   256
#define EPT   (NFFT / TPB)        // 8 elements per thread
#define MAXB  64
#define NS    81                  // number of scales (J=80 -> 81)
#define WSZ   94                  // sliding window = 32*3 - 2
#define NOUT  (NFFT - WSZ + 1)    // 1955

#define PI_F  3.14159265358979323846f
#define TWO_PI_F 6.28318530717958647692f

// SMEM padding: 1 extra float2 per 8 -> conflict-free radix-8 exchanges
#define PIDX(i) ((i) + ((i) >> 3))
#define PADN  2304                // PIDX(2047)+1 = 2303, rounded
#define SMEM_DYN (4 * PADN * (int)sizeof(float2))   // 73728 B: ping+pong per stream

// ---------------- scratch (static device globals; no runtime alloc) ----------
__device__ float2 g_tw[256];                      // twiddles e^{-i pi j / 1024}
__device__ float2 g_yh[MAXB * 2 * NFFT];          // forward FFT of normalized inputs
// bf16-packed smooth outputs: [b][scale][t][0] = bf16x2(T1,T2), [1] = bf16x2(T12r,T12i)
__device__ unsigned int g_Tb[(size_t)MAXB * NS * NFFT * 2];
__device__ float  g_coh[MAXB * NFFT];             // coherence summed over scales

// ---------------- complex helpers ---------------------------------------------
__device__ __forceinline__ float2 cadd(float2 a, float2 b){ return make_float2(a.x+b.x, a.y+b.y); }
__device__ __forceinline__ float2 csub(float2 a, float2 b){ return make_float2(a.x-b.x, a.y-b.y); }
__device__ __forceinline__ float2 cmul(float2 a, float2 b){
  return make_float2(a.x*b.x - a.y*b.y, a.x*b.y + a.y*b.x);
}
// multiply by -i (forward) or +i (inverse)
__device__ __forceinline__ float2 rotm(float2 a, bool inv){
  return inv ? make_float2(-a.y, a.x) : make_float2(a.y, -a.x);
}

// second half of the radix-8 butterfly given t0..t7 (t5,t6,t7 already rotated)
__device__ __forceinline__ void bfly8_tail(float2 t0, float2 t1, float2 t2, float2 t3,
                                           float2 t4, float2 t5, float2 t6, float2 t7,
                                           float2* b, bool inv) {
  float2 u0 = cadd(t0,t2), u2 = csub(t0,t2);
  float2 u1 = cadd(t1,t3), u3 = rotm(csub(t1,t3), inv);
  b[0] = cadd(u0,u1); b[4] = csub(u0,u1);
  b[2] = cadd(u2,u3); b[6] = csub(u2,u3);

  float2 v0 = cadd(t4,t6), v2 = csub(t4,t6);
  float2 v1 = cadd(t5,t7), v3 = rotm(csub(t5,t7), inv);
  b[1] = cadd(v0,v1); b[5] = csub(v0,v1);
  b[3] = cadd(v2,v3); b[7] = csub(v2,v3);
}

__device__ __forceinline__ void bfly8(const float2* a, float2* b, bool inv) {
  const float C = 0.70710678118654752440f;
  float2 t0 = cadd(a[0],a[4]), t4 = csub(a[0],a[4]);
  float2 t1 = cadd(a[1],a[5]), t5 = csub(a[1],a[5]);
  float2 t2 = cadd(a[2],a[6]), t6 = csub(a[2],a[6]);
  float2 t3 = cadd(a[3],a[7]), t7 = csub(a[3],a[7]);
  const float2 w81 = inv ? make_float2(C,  C) : make_float2(C, -C);
  const float2 w83 = inv ? make_float2(-C, C) : make_float2(-C,-C);
  bfly8_tail(t0, t1, t2, t3, t4, cmul(t5, w81), rotm(t6, inv), cmul(t7, w83), b, inv);
}

// radix-8 butterfly with a[4..7] == 0 (half-spectrum inverse first stage)
__device__ __forceinline__ void bfly8_half(const float2* a, float2* b, bool inv) {
  const float C = 0.70710678118654752440f;
  const float2 w81 = inv ? make_float2(C,  C) : make_float2(C, -C);
  const float2 w83 = inv ? make_float2(-C, C) : make_float2(-C,-C);
  bfly8_tail(a[0], a[1], a[2], a[3], a[0], cmul(a[1], w81), rotm(a[2], inv), cmul(a[3], w83), b, inv);
}

struct W7 { float2 w1,w2,w3,w4,w5,w6,w7; };
__device__ __forceinline__ W7 make_w7(float2 w1) {
  W7 w;
  w.w1 = w1;
  w.w2 = cmul(w1, w1);
  w.w3 = cmul(w.w2, w1);
  w.w4 = cmul(w.w2, w.w2);
  w.w5 = cmul(w.w3, w.w2);
  w.w6 = cmul(w.w3, w.w3);
  w.w7 = cmul(w.w4, w.w3);
  return w;
}
__device__ __forceinline__ void apply_w7(float2* b, const W7& w) {
  b[1] = cmul(b[1], w.w1); b[2] = cmul(b[2], w.w2); b[3] = cmul(b[3], w.w3);
  b[4] = cmul(b[4], w.w4); b[5] = cmul(b[5], w.w5); b[6] = cmul(b[6], w.w6);
  b[7] = cmul(b[7], w.w7);
}

// ================= single-stream FFT (used by K1) ===============================
template<bool HALF>
__device__ __forceinline__ void stage1_reg(const float2* x, float2* dst,
                                           const float2* __restrict__ tw, int tid, bool inv) {
  float2 b[8];
  if (HALF) bfly8_half(x, b, inv); else bfly8(x, b, inv);
  float2 w1 = tw[tid];
  if (inv) w1.y = -w1.y;
  W7 w = make_w7(w1);
  apply_w7(b, w);
  const int wb = 8 * tid;
  #pragma unroll
  for (int j = 0; j < 8; ++j) dst[PIDX(wb + j)] = b[j];
}

template<int S>
__device__ __forceinline__ void stage8(const float2* __restrict__ src, float2* __restrict__ dst,
                                       const float2* __restrict__ tw, int tid, bool inv) {
  const int p = tid / S;
  const int q = tid - p * S;
  const int rb = q + S * p;

  float2 a[8];
  #pragma unroll
  for (int k = 0; k < 8; ++k) a[k] = src[PIDX(rb + 256 * k)];

  float2 b[8];
  bfly8(a, b, inv);
  float2 w1 = tw[p * S];
  if (inv) w1.y = -w1.y;
  W7 w = make_w7(w1);
  apply_w7(b, w);

  const int wb = q + S * 8 * p;
  #pragma unroll
  for (int j = 0; j < 8; ++j) dst[PIDX(wb + j * S)] = b[j];
}

__device__ __forceinline__ void stage4_reg(const float2* __restrict__ src, float2* y,
                                           int tid, bool inv) {
  #pragma unroll
  for (int rr = 0; rr < 2; ++rr) {
    const int q = tid + rr * TPB;
    float2 a0 = src[PIDX(q)];
    float2 a1 = src[PIDX(q +  512)];
    float2 a2 = src[PIDX(q + 1024)];
    float2 a3 = src[PIDX(q + 1536)];
    float2 t0 = cadd(a0,a2), t1 = csub(a0,a2);
    float2 t2 = cadd(a1,a3), t3 = rotm(csub(a1,a3), inv);
    y[rr + 0] = cadd(t0,t2);   // element q
    y[rr + 2] = cadd(t1,t3);   // element q + 512
    y[rr + 4] = csub(t0,t2);   // element q + 1024
    y[rr + 6] = csub(t1,t3);   // element q + 1536
  }
}

template<bool HALF>
__device__ __forceinline__ void fft_reg(float2* x, float2* sA, float2* sB,
                                        const float2* __restrict__ tw, int tid, bool inv) {
  __syncthreads();
  stage1_reg<HALF>(x, sB, tw, tid, inv);  __syncthreads();
  stage8<8> (sB, sA, tw, tid, inv); __syncthreads();
  stage8<64>(sA, sB, tw, tid, inv); __syncthreads();
  stage4_reg(sB, x, tid, inv);
}

// ================= dual-stream ping-pong FFT (used by K2) =======================
template<bool HALF>
__device__ __forceinline__ void stage1_dual(const float2* x1, const float2* x2,
                                            float2* d1, float2* d2,
                                            const float2* __restrict__ tw, int tid, bool inv) {
  float2 b1[8], b2[8];
  if (HALF) { bfly8_half(x1, b1, inv); bfly8_half(x2, b2, inv); }
  else      { bfly8(x1, b1, inv);      bfly8(x2, b2, inv); }
  float2 w1 = tw[tid];
  if (inv) w1.y = -w1.y;
  W7 w = make_w7(w1);
  apply_w7(b1, w);
  apply_w7(b2, w);
  const int wb = 8 * tid;
  #pragma unroll
  for (int j = 0; j < 8; ++j) { d1[PIDX(wb + j)] = b1[j]; d2[PIDX(wb + j)] = b2[j]; }
}

template<int S>
__device__ __forceinline__ void stage8_dual_pp(const float2* __restrict__ s1,
                                               const float2* __restrict__ s2,
                                               float2* __restrict__ d1,
                                               float2* __restrict__ d2,
                                               const float2* __restrict__ tw, int tid, bool inv) {
  const int p = tid / S;
  const int q = tid - p * S;
  const int rb = q + S * p;

  float2 a1[8], a2[8];
  #pragma unroll
  for (int k = 0; k < 8; ++k) {
    a1[k] = s1[PIDX(rb + 256 * k)];
    a2[k] = s2[PIDX(rb + 256 * k)];
  }

  float2 b1[8], b2[8];
  bfly8(a1, b1, inv);
  bfly8(a2, b2, inv);
  float2 w1 = tw[p * S];
  if (inv) w1.y = -w1.y;
  W7 w = make_w7(w1);
  apply_w7(b1, w);
  apply_w7(b2, w);

  const int wb = q + S * 8 * p;
  #pragma unroll
  for (int j = 0; j < 8; ++j) {
    d1[PIDX(wb + j * S)] = b1[j];
    d2[PIDX(wb + j * S)] = b2[j];
  }
}

__device__ __forceinline__ void stage4_dual(const float2* s1, const float2* s2,
                                            float2* y1, float2* y2, int tid, bool inv) {
  #pragma unroll
  for (int rr = 0; rr < 2; ++rr) {
    const int q = tid + rr * TPB;
    {
      float2 a0 = s1[PIDX(q)],        a1 = s1[PIDX(q +  512)];
      float2 a2 = s1[PIDX(q + 1024)], a3 = s1[PIDX(q + 1536)];
      float2 t0 = cadd(a0,a2), t1 = csub(a0,a2);
      float2 t2 = cadd(a1,a3), t3 = rotm(csub(a1,a3), inv);
      y1[rr + 0] = cadd(t0,t2); y1[rr + 2] = cadd(t1,t3);
      y1[rr + 4] = csub(t0,t2); y1[rr + 6] = csub(t1,t3);
    }
    {
      float2 a0 = s2[PIDX(q)],        a1 = s2[PIDX(q +  512)];
      float2 a2 = s2[PIDX(q + 1024)], a3 = s2[PIDX(q + 1536)];
      float2 t0 = cadd(a0,a2), t1 = csub(a0,a2);
      float2 t2 = cadd(a1,a3), t3 = rotm(csub(a1,a3), inv);
      y2[rr + 0] = cadd(t0,t2); y2[rr + 2] = cadd(t1,t3);
      y2[rr + 4] = csub(t0,t2); y2[rr + 6] = csub(t1,t3);
    }
  }
}

// buffers: pA/pB = stream-1 ping/pong, qA/qB = stream-2 ping/pong
template<bool HALF>
__device__ __forceinline__ void fft_dual(float2* x1, float2* x2,
                                         float2* pA, float2* qA, float2* pB, float2* qB,
                                         const float2* __restrict__ tw, int tid, bool inv) {
  __syncthreads();                                   // ping free of previous readers
  stage1_dual<HALF>(x1, x2, pA, qA, tw, tid, inv);
  __syncthreads();
  stage8_dual_pp<8> (pA, qA, pB, qB, tw, tid, inv);
  __syncthreads();
  stage8_dual_pp<64>(pB, qB, pA, qA, tw, tid, inv);
  __syncthreads();
  stage4_dual(pA, qA, x1, x2, tid, inv);
}

// ---------------- K0: build 256-entry twiddle table (double precision) ---------
__global__ void kern_init_tw() {
  const int j = threadIdx.x;
  double a = -3.14159265358979323846 * (double)j / 1024.0;
  g_tw[j] = make_float2((float)cos(a), (float)sin(a));
}

// ---------------- K1: normalize + forward FFT of each input signal ------------
__global__ void kern_fft_input(const float* __restrict__ x) {
  __shared__ float2 sA[PADN];
  __shared__ float2 sB[PADN];
  __shared__ float2 tw[256];
  __shared__ float  red[TPB];
  const int bc  = blockIdx.x;   // b*2 + channel
  const int tid = threadIdx.x;

  tw[tid] = g_tw[tid];

  const float* y = x + (size_t)bc * NFFT;
  float vals[EPT];
  float sum = 0.f, sumsq = 0.f;
  #pragma unroll
  for (int r = 0; r < EPT; ++r) {
    float v = y[tid + r * TPB];
    vals[r] = v;
    sum += v;
    sumsq += v * v;
  }
  red[tid] = sum; __syncthreads();
  for (int o = TPB / 2; o > 0; o >>= 1) { if (tid < o) red[tid] += red[tid + o]; __syncthreads(); }
  float mean = red[0] * (1.0f / NFFT);
  __syncthreads();
  red[tid] = sumsq; __syncthreads();
  for (int o = TPB / 2; o > 0; o >>= 1) { if (tid < o) red[tid] += red[tid + o]; __syncthreads(); }
  float var = red[0] * (1.0f / NFFT) - mean * mean;
  float istd = rsqrtf(var);

  float2 z[EPT];
  #pragma unroll
  for (int r = 0; r < EPT; ++r)
    z[r] = make_float2((vals[r] - mean) * istd, 0.f);

  fft_reg<false>(z, sA, sB, tw, tid, false);

  #pragma unroll
  for (int r = 0; r < EPT; ++r)
    g_yh[(size_t)bc * NFFT + tid + r * TPB] = z[r];
}

// ---------------- K2: per (batch, scale) CWT + time smoothing -----------------
__global__ void __launch_bounds__(TPB) kern_scale() {
  extern __shared__ float2 dyn[];
  float2* pA = dyn;
  float2* qA = dyn + PADN;
  float2* pB = dyn + 2 * PADN;
  float2* qB = dyn + 3 * PADN;
  __shared__ float2 tw[256];
  const int si  = blockIdx.x;   // scale index
  const int b   = blockIdx.y;   // batch
  const int tid = threadIdx.x;

  tw[tid] = g_tw[tid];

  const double s0d = 2.0 * 0.1 * (6.0 + sqrt(38.0)) / (4.0 * 3.14159265358979323846);
  const float  sc    = (float)(s0d * exp2(0.125 * (double)si));
  const float  inv_s = 1.0f / sc;
  const float  norm  = sqrtf(TWO_PI_F * sc * 10.0f) * 0.75112554446494248f;
  const float  sdt   = sc * 10.0f;
  const float  INVN  = 1.0f / (float)NFFT;
  const float  pscale = INVN * INVN * inv_s;   // 1/N per ifft (x2) and 1/s

  float2 x1[EPT], x2[EPT];

  // --- W1, W2 (unscaled by 1/N): ifft( yh * norm * psi_hat ), support k in [1,1023]
  #pragma unroll
  for (int c = 0; c < 2; ++c) {
    float2* xx = c == 0 ? x1 : x2;
    #pragma unroll
    for (int r = 0; r < 4; ++r) {        // only k < 1024 nonzero
      int k = tid + r * TPB;
      float2 v = make_float2(0.f, 0.f);
      if (k >= 1) {
        float w = TWO_PI_F * (float)k * (1.0f / 204.8f);
        float d = sc * w - 6.0f;
        float g = norm * __expf(-0.5f * d * d);
        float2 yh = g_yh[(size_t)(b * 2 + c) * NFFT + k];
        v = make_float2(yh.x * g, yh.y * g);
      }
      xx[r] = v;
    }
    #pragma unroll
    for (int r = 4; r < EPT; ++r) xx[r] = make_float2(0.f, 0.f);
  }
  fft_dual<true>(x1, x2, pA, qA, pB, qB, tw, tid, true);

  // --- products: P = (|W1|^2 + i|W2|^2)*pscale in x1, C = W1*conj(W2)*pscale in x2
  #pragma unroll
  for (int r = 0; r < EPT; ++r) {
    float2 a = x1[r], bb = x2[r];
    x1[r] = make_float2((a.x * a.x + a.y * a.y) * pscale,
                        (bb.x * bb.x + bb.y * bb.y) * pscale);
    x2[r] = make_float2((a.x * bb.x + a.y * bb.y) * pscale,
                        (a.y * bb.x - a.x * bb.y) * pscale);
  }

  const size_t base = ((size_t)b * NS + si) * NFFT;

  fft_dual<false>(x1, x2, pA, qA, pB, qB, tw, tid, false);

  // Gaussian time-filter (incl. 1/N for the subsequent inverse FFT)
  #pragma unroll
  for (int r = 0; r < EPT; ++r) {
    int k = tid + r * TPB;
    float fk = (float)(k < NFFT / 2 ? k : k - NFFT) * (1.0f / NFFT);
    float kk = TWO_PI_F * fk;
    float F = __expf(-0.5f * sdt * sdt * kk * kk) * INVN;
    x1[r] = make_float2(x1[r].x * F, x1[r].y * F);
    x2[r] = make_float2(x2[r].x * F, x2[r].y * F);
  }

  fft_dual<false>(x1, x2, pA, qA, pB, qB, tw, tid, true);

  // --- stores (bf16x2 packed: halves DRAM traffic here and in K3)
  #pragma unroll
  for (int r = 0; r < EPT; ++r) {
    const size_t idx = base + tid + r * TPB;
    __nv_bfloat162 t12 = __float22bfloat162_rn(x1[r]);   // (T1, T2)
    __nv_bfloat162 c12 = __float22bfloat162_rn(x2[r]);   // (T12r, T12i)
    g_Tb[idx * 2]     = *reinterpret_cast<unsigned int*>(&t12);
    g_Tb[idx * 2 + 1] = *reinterpret_cast<unsigned int*>(&c12);
  }
}

// ---------------- K3: scale smoothing + coherence + sum over scales -----------
// Pair-split: even lane of each pair carries (T1,T2), odd lane carries T12.
// Window along scales: [.5,1,...,1,.5] at offsets i-5..i+4 (clipped); the 1/9
// normalization cancels. Ring depth 10; outgoing element retired BEFORE the
// incoming one overwrites its shared slot. Division replaced by MUFU.RCP on
// the even lane + one shfl + FMA on both lanes. Loads are packed bf16x2.
__global__ void __launch_bounds__(TPB) kern_coh() {
  const int b   = blockIdx.y;
  const int sub = threadIdx.x & 1;                    // 0: (T1,T2), 1: T12
  const int t   = blockIdx.x * (TPB / 2) + (threadIdx.x >> 1);
  const size_t base = ((size_t)b * NS * NFFT + t) * 2 + sub;
  const size_t step = (size_t)NFFT * 2;

  float ru[10], rv[10];
  float su = 0.f, sv = 0.f;

  #pragma unroll
  for (int j = 0; j < 4; ++j) {
    unsigned int pv = g_Tb[base + (size_t)j * step];
    float2 d = __bfloat1622float2(*reinterpret_cast<__nv_bfloat162*>(&pv));
    ru[j] = d.x; rv[j] = d.y; su += d.x; sv += d.y;
  }

  float acc = 0.f;
  #pragma unroll
  for (int i = 0; i < NS; ++i) {
    const int jo = i - 6;
    if (jo >= 0) {
      const int ro = jo % 10;
      su -= ru[ro]; sv -= rv[ro];
    }
    const int jn = i + 4;
    if (jn < NS) {
      unsigned int pv = g_Tb[base + (size_t)jn * step];
      float2 d = __bfloat1622float2(*reinterpret_cast<__nv_bfloat162*>(&pv));
      const int rn = jn % 10;
      ru[rn] = d.x; rv[rn] = d.y; su += d.x; sv += d.y;
    }
    float eu = su, ev = sv;
    const int jl = i - 5;
    if (jl >= 0) {
      const int rl = jl % 10;
      eu -= 0.5f * ru[rl]; ev -= 0.5f * rv[rl];
    }
    if (jn < NS) {
      const int rn = jn % 10;
      eu -= 0.5f * ru[rn]; ev -= 0.5f * rv[rn];
    }
    float val = sub ? (eu * eu + ev * ev) : __fdividef(1.0f, eu * ev);
    float other = __shfl_xor_sync(0xffffffffu, val, 1);
    acc += val * other;
  }
  if (!sub) g_coh[(size_t)b * NFFT + t] = acc;
}

// ---------------- K4: sliding window sum (WSZ=94), incremental -----------------
__global__ void __launch_bounds__(TPB) kern_slide(float* __restrict__ out) {
  __shared__ float sc[NFFT];
  __shared__ float so[NOUT];
  const int b = blockIdx.x;
  const int tid = threadIdx.x;
  #pragma unroll
  for (int r = 0; r < EPT; ++r)
    sc[tid + r * TPB] = g_coh[(size_t)b * NFFT + tid + r * TPB];
  __syncthreads();

  const int i0 = tid * 8;
  if (i0 < NOUT) {
    float s = 0.f;
    #pragma unroll
    for (int k = 0; k < WSZ; ++k) s += sc[i0 + k];
    so[i0] = s;
    const int lim = (NOUT - i0 < 8) ? (NOUT - i0) : 8;
    for (int r = 1; r < lim; ++r) {
      s += sc[i0 + r - 1 + WSZ] - sc[i0 + r - 1];
      so[i0 + r] = s;
    }
  }
  __syncthreads();
  for (int i = tid; i < NOUT; i += TPB)
    out[(size_t)b * NOUT + i] = so[i];
}

// ---------------- launch -------------------------------------------------------
extern "C" void kernel_launch(void* const* d_in, const int* in_sizes, int n_in,
                              void* d_out, int out_size) {
  const float* x = (const float*)d_in[0];
  int B = in_sizes[0] / (2 * NFFT);
  if (B > MAXB) B = MAXB;
  if (B <= 0) return;

  cudaFuncSetAttribute(kern_scale, cudaFuncAttributeMaxDynamicSharedMemorySize, SMEM_DYN);

  kern_init_tw<<<1, 256>>>();
  kern_fft_input<<<B * 2, TPB>>>(x);
  kern_scale<<<dim3(NS, B), TPB, SMEM_DYN>>>();
  kern_coh<<<dim3(NFFT / (TPB / 2), B), TPB>>>();
  kern_slide<<<B, TPB>>>((float*)d_out);
}